// round 4
// baseline (speedup 1.0000x reference)
#include <cuda_runtime.h>
#include <cuda_bf16.h>
#include <cstdint>
#include <math.h>

#define T_DIM 64
#define B_DIM 512
#define D_DIM 1536
#define H_DIM 1024
#define M_DIM 32768
#define DISCOUNT 0.997f
#define LAM 0.95f

#define W_TOTAL (D_DIM * H_DIM + 3 * H_DIM * H_DIM)

// ---- allocation-free scratch ----
__device__ __nv_bfloat16 g_fhi [(size_t)M_DIM * D_DIM];
__device__ __nv_bfloat16 g_fmid[(size_t)M_DIM * D_DIM];
__device__ __nv_bfloat16 g_ahi [2][(size_t)M_DIM * H_DIM];
__device__ __nv_bfloat16 g_amid[2][(size_t)M_DIM * H_DIM];
__device__ __nv_bfloat16 g_whi [W_TOTAL];
__device__ __nv_bfloat16 g_wmid[W_TOTAL];
__device__ float g_partial[32 * (size_t)M_DIM];

// ---- helpers ----
__device__ __forceinline__ uint32_t smem_to_u32(const void* p) {
    uint32_t a;
    asm("{ .reg .u64 t; cvta.to.shared.u64 t, %1; cvt.u32.u64 %0, t; }" : "=r"(a) : "l"(p));
    return a;
}
__device__ __forceinline__ float bf16_rn(float x) { return __bfloat162float(__float2bfloat16(x)); }
// pack: lo -> low half, hi -> high half
__device__ __forceinline__ uint32_t packbf(float lo, float hi) {
    uint32_t r;
    asm("cvt.rn.bf16x2.f32 %0, %1, %2;" : "=r"(r) : "f"(hi), "f"(lo));
    return r;
}
__device__ __forceinline__ float silu(float x) { return x / (1.0f + expf(-x)); }

__device__ __forceinline__ void mma16816(float* d, const uint32_t* a, const uint32_t* b) {
    asm volatile(
        "mma.sync.aligned.m16n8k16.row.col.f32.bf16.bf16.f32 "
        "{%0,%1,%2,%3}, {%4,%5,%6,%7}, {%8,%9}, {%0,%1,%2,%3};"
        : "+f"(d[0]), "+f"(d[1]), "+f"(d[2]), "+f"(d[3])
        : "r"(a[0]), "r"(a[1]), "r"(a[2]), "r"(a[3]), "r"(b[0]), "r"(b[1]));
}
#define LDSM4(r, addr) \
    asm volatile("ldmatrix.sync.aligned.m8n8.x4.shared.b16 {%0,%1,%2,%3}, [%4];" \
        : "=r"((r)[0]), "=r"((r)[1]), "=r"((r)[2]), "=r"((r)[3]) : "r"(addr))
#define CP16(dst, src) \
    asm volatile("cp.async.cg.shared.global [%0], [%1], 16;" :: "r"(dst), "l"(src))
#define CP_COMMIT asm volatile("cp.async.commit_group;" ::: "memory")
#define CP_WAIT1  asm volatile("cp.async.wait_group 1;" ::: "memory")

// ---------------------------------------------------------------------------
// splitter: fp32 -> bf16 hi/mid planes (same flat layout)
// ---------------------------------------------------------------------------
__global__ void __launch_bounds__(256)
split_kernel(const float* __restrict__ src, __nv_bfloat16* __restrict__ hi,
             __nv_bfloat16* __restrict__ mid, size_t n4)
{
    size_t i = (size_t)blockIdx.x * blockDim.x + threadIdx.x;
    const size_t stride = (size_t)gridDim.x * blockDim.x;
    const float4* s4 = (const float4*)src;
    uint32_t* h2 = (uint32_t*)hi;
    uint32_t* m2 = (uint32_t*)mid;
    for (; i < n4; i += stride) {
        float4 v = s4[i];
        float hx = bf16_rn(v.x), hy = bf16_rn(v.y), hz = bf16_rn(v.z), hw = bf16_rn(v.w);
        h2[i * 2]     = packbf(hx, hy);
        h2[i * 2 + 1] = packbf(hz, hw);
        m2[i * 2]     = packbf(v.x - hx, v.y - hy);
        m2[i * 2 + 1] = packbf(v.z - hz, v.w - hw);
    }
}

// ---------------------------------------------------------------------------
// weight splitter + transpose: W[K,N] fp32 -> Wt_hi/Wt_mid [N,K] bf16
// ---------------------------------------------------------------------------
__global__ void __launch_bounds__(256)
split_wt_kernel(const float* __restrict__ W, __nv_bfloat16* __restrict__ whi,
                __nv_bfloat16* __restrict__ wmid, int K, int N)
{
    __shared__ float t[32][33];
    const int k0 = blockIdx.y * 32, n0 = blockIdx.x * 32;
    const int tx = threadIdx.x, ty = threadIdx.y;   // (32, 8)
    #pragma unroll
    for (int j = 0; j < 32; j += 8)
        t[ty + j][tx] = W[(size_t)(k0 + ty + j) * N + n0 + tx];
    __syncthreads();
    #pragma unroll
    for (int j = 0; j < 32; j += 8) {
        const float v = t[tx][ty + j];
        const float h = bf16_rn(v);
        const size_t o = (size_t)(n0 + ty + j) * K + k0 + tx;
        whi[o]  = __float2bfloat16(v);
        wmid[o] = __float2bfloat16(v - h);
    }
}

// ---------------------------------------------------------------------------
// GEMM: 128x128 tile, 8 warps (2m x 4n), cp.async 3-stage, ldmatrix, 3xBF16.
// smem per stage: A_hi, A_mid, B_hi, B_mid, each 128 rows x 64 B (swizzled).
// ---------------------------------------------------------------------------
#define CHUNK 32                 // K halves per stage
#define PLANE_B 8192
#define STAGE_B (4 * PLANE_B)    // 32 KB
#define NSTAGE 3
#define SMEM_BYTES (NSTAGE * STAGE_B)   // 96 KB

__global__ void __launch_bounds__(256, 1)
gemm_hmma(const __nv_bfloat16* __restrict__ Ahi, const __nv_bfloat16* __restrict__ Amid,
          const __nv_bfloat16* __restrict__ Bhi, const __nv_bfloat16* __restrict__ Bmid,
          const float* __restrict__ bias,
          __nv_bfloat16* __restrict__ Chi, __nv_bfloat16* __restrict__ Cmid,
          const float* __restrict__ Wo, float* __restrict__ partial,
          int K, int mode)
{
    extern __shared__ char smem[];
    const uint32_t sb = smem_to_u32(smem);
    const int tid  = threadIdx.x;
    const int wid  = tid >> 5;
    const int lane = tid & 31;
    const int row0 = blockIdx.y * 128;
    const int col0 = blockIdx.x * 128;
    const int wm = wid & 1;       // 2 m-warps
    const int wn = wid >> 1;      // 4 n-warps

    // cp.async mapping: thread -> (row, 2 chunks of 16B) per plane
    const int r_ld = tid >> 1;             // 0..127
    const int cb   = (tid & 1) * 2;        // chunk base 0 or 2
    const int xr   = (r_ld >> 1) & 3;
    const uint32_t d0 = (uint32_t)(r_ld * 64 + (((cb    ) ^ xr) << 4));
    const uint32_t d1 = (uint32_t)(r_ld * 64 + (((cb + 1) ^ xr) << 4));

    const __nv_bfloat16* sAh = Ahi  + (size_t)(row0 + r_ld) * K + cb * 8;
    const __nv_bfloat16* sAm = Amid + (size_t)(row0 + r_ld) * K + cb * 8;
    const __nv_bfloat16* sBh = Bhi  + (size_t)(col0 + r_ld) * K + cb * 8;
    const __nv_bfloat16* sBm = Bmid + (size_t)(col0 + r_ld) * K + cb * 8;

    float acc[4][4][4];
    #pragma unroll
    for (int i = 0; i < 4; i++)
        #pragma unroll
        for (int j = 0; j < 4; j++)
            #pragma unroll
            for (int c = 0; c < 4; c++) acc[i][j][c] = 0.0f;

    const int nk = K / CHUNK;

    auto issue = [&](int kt) {
        const uint32_t base = sb + (kt % NSTAGE) * STAGE_B;
        const size_t ko = (size_t)kt * CHUNK;
        CP16(base + d0,               sAh + ko); CP16(base + d1,               sAh + ko + 8);
        CP16(base + PLANE_B + d0,     sAm + ko); CP16(base + PLANE_B + d1,     sAm + ko + 8);
        CP16(base + 2 * PLANE_B + d0, sBh + ko); CP16(base + 2 * PLANE_B + d1, sBh + ko + 8);
        CP16(base + 3 * PLANE_B + d0, sBm + ko); CP16(base + 3 * PLANE_B + d1, sBm + ko + 8);
    };

    issue(0); CP_COMMIT;
    issue(1); CP_COMMIT;

    // lane-fixed fragment address pieces
    const int ra_base = wm * 64 + (lane & 15);                        // + mi*16
    const int rb_base = wn * 32 + ((lane >> 4) << 3) + (lane & 7);    // + nt*16
    const int ca_sel  = lane >> 4;                                    // chunk add for A
    const int cb_sel  = (lane >> 3) & 1;                              // chunk add for B

    for (int kt = 0; kt < nk; kt++) {
        CP_WAIT1;
        __syncthreads();
        if (kt + 2 < nk) issue(kt + 2);
        CP_COMMIT;

        const uint32_t base = sb + (kt % NSTAGE) * STAGE_B;
        #pragma unroll
        for (int ks = 0; ks < 2; ks++) {
            uint32_t a[4][2][4], b[2][2][4];
            #pragma unroll
            for (int mi = 0; mi < 4; mi++) {
                const int r = ra_base + mi * 16;
                const int c = ks * 2 + ca_sel;
                const uint32_t off = (uint32_t)(r * 64 + ((c ^ ((r >> 1) & 3)) << 4));
                LDSM4(a[mi][0], base + off);
                LDSM4(a[mi][1], base + PLANE_B + off);
            }
            #pragma unroll
            for (int nt = 0; nt < 2; nt++) {
                const int r = rb_base + nt * 16;
                const int c = ks * 2 + cb_sel;
                const uint32_t off = (uint32_t)(r * 64 + ((c ^ ((r >> 1) & 3)) << 4));
                LDSM4(b[nt][0], base + 2 * PLANE_B + off);
                LDSM4(b[nt][1], base + 3 * PLANE_B + off);
            }
            #pragma unroll
            for (int mi = 0; mi < 4; mi++)
                #pragma unroll
                for (int nt = 0; nt < 2; nt++)
                    #pragma unroll
                    for (int h = 0; h < 2; h++) {
                        float* d = acc[mi][nt * 2 + h];
                        mma16816(d, a[mi][0], &b[nt][0][h * 2]);   // hi*hi
                        mma16816(d, a[mi][0], &b[nt][1][h * 2]);   // hi*mid
                        mma16816(d, a[mi][1], &b[nt][0][h * 2]);   // mid*hi
                    }
        }
    }

    // ---- epilogue ----
    if (mode == 0) {
        #pragma unroll
        for (int mi = 0; mi < 4; mi++) {
            const int grow = row0 + wm * 64 + mi * 16 + (lane >> 2);
            #pragma unroll
            for (int ni = 0; ni < 4; ni++) {
                const int gcol = col0 + wn * 32 + (ni >> 1) * 16 + (ni & 1) * 8 + (lane & 3) * 2;
                const float b0 = bias[gcol], b1 = bias[gcol + 1];
                float x0 = silu(acc[mi][ni][0] + b0);
                float x1 = silu(acc[mi][ni][1] + b1);
                float x2 = silu(acc[mi][ni][2] + b0);
                float x3 = silu(acc[mi][ni][3] + b1);
                float h0 = bf16_rn(x0), h1 = bf16_rn(x1), h2 = bf16_rn(x2), h3 = bf16_rn(x3);
                const size_t o0 = (size_t)grow * H_DIM + gcol;
                const size_t o1 = (size_t)(grow + 8) * H_DIM + gcol;
                *(uint32_t*)(Chi  + o0) = packbf(h0, h1);
                *(uint32_t*)(Cmid + o0) = packbf(x0 - h0, x1 - h1);
                *(uint32_t*)(Chi  + o1) = packbf(h2, h3);
                *(uint32_t*)(Cmid + o1) = packbf(x2 - h2, x3 - h3);
            }
        }
    } else {
        const int p = blockIdx.x * 4 + wn;
        #pragma unroll
        for (int mi = 0; mi < 4; mi++) {
            float s0 = 0.0f, s1 = 0.0f;
            #pragma unroll
            for (int ni = 0; ni < 4; ni++) {
                const int gcol = col0 + wn * 32 + (ni >> 1) * 16 + (ni & 1) * 8 + (lane & 3) * 2;
                const float b0 = bias[gcol], b1 = bias[gcol + 1];
                const float w0 = Wo[gcol], w1 = Wo[gcol + 1];
                s0 += silu(acc[mi][ni][0] + b0) * w0 + silu(acc[mi][ni][1] + b1) * w1;
                s1 += silu(acc[mi][ni][2] + b0) * w0 + silu(acc[mi][ni][3] + b1) * w1;
            }
            s0 += __shfl_xor_sync(0xffffffffu, s0, 1);
            s0 += __shfl_xor_sync(0xffffffffu, s0, 2);
            s1 += __shfl_xor_sync(0xffffffffu, s1, 1);
            s1 += __shfl_xor_sync(0xffffffffu, s1, 2);
            if ((lane & 3) == 0) {
                const int r = row0 + wm * 64 + mi * 16 + (lane >> 2);
                partial[(size_t)p * M_DIM + r]     = s0;
                partial[(size_t)p * M_DIM + r + 8] = s1;
            }
        }
    }
}

// ---------------------------------------------------------------------------
// GAE reverse scan; value[m] = sum of 32 partials + bo.
// ---------------------------------------------------------------------------
__global__ void __launch_bounds__(256)
scan_kernel(const float* __restrict__ reward, const float* __restrict__ cont,
            const float* __restrict__ partial, const float* __restrict__ bo,
            float* __restrict__ out)
{
    const int b = blockIdx.x * blockDim.x + threadIdx.x;
    if (b >= B_DIM) return;
    const float bov = bo[0];

    auto val = [&](int m) {
        float s = 0.0f;
        #pragma unroll
        for (int c = 0; c < 32; c++) s += partial[(size_t)c * M_DIM + m];
        return s + bov;
    };

    float adv = 0.0f;
    float v_next = val((T_DIM - 1) * B_DIM + b);
    for (int t = T_DIM - 2; t >= 0; t--) {
        const float v0   = val(t * B_DIM + b);
        const float disc = cont[(t + 1) * B_DIM + b] * DISCOUNT;
        const float dl   = disc * LAM;
        const float delta = reward[t * B_DIM + b] + disc * v_next - v0;
        adv = delta + dl * adv;
        out[t * B_DIM + b] = adv + v0;                       // ret
        out[(T_DIM - 1) * B_DIM + t * B_DIM + b] = v0;       // baseline
        v_next = v0;
    }
}

// ---------------------------------------------------------------------------
extern "C" void kernel_launch(void* const* d_in, const int* in_sizes, int n_in,
                              void* d_out, int out_size)
{
    const float* feat   = (const float*)d_in[0];
    const float* reward = (const float*)d_in[1];
    const float* cont   = (const float*)d_in[2];
    const float* W0 = (const float*)d_in[3];
    const float* b0 = (const float*)d_in[4];
    const float* W1 = (const float*)d_in[5];
    const float* b1 = (const float*)d_in[6];
    const float* W2 = (const float*)d_in[7];
    const float* b2 = (const float*)d_in[8];
    const float* W3 = (const float*)d_in[9];
    const float* b3 = (const float*)d_in[10];
    const float* Wo = (const float*)d_in[11];
    const float* bo = (const float*)d_in[12];
    float* out = (float*)d_out;

    __nv_bfloat16 *fhi, *fmid, *ahi, *amid, *whi, *wmid;
    float *part;
    cudaGetSymbolAddress((void**)&fhi,  g_fhi);
    cudaGetSymbolAddress((void**)&fmid, g_fmid);
    cudaGetSymbolAddress((void**)&ahi,  g_ahi);
    cudaGetSymbolAddress((void**)&amid, g_amid);
    cudaGetSymbolAddress((void**)&whi,  g_whi);
    cudaGetSymbolAddress((void**)&wmid, g_wmid);
    cudaGetSymbolAddress((void**)&part, g_partial);

    const size_t AHALF = (size_t)M_DIM * H_DIM;
    const size_t wo0 = 0;
    const size_t wo1 = (size_t)D_DIM * H_DIM;
    const size_t wo2 = wo1 + (size_t)H_DIM * H_DIM;
    const size_t wo3 = wo2 + (size_t)H_DIM * H_DIM;

    cudaFuncSetAttribute(gemm_hmma, cudaFuncAttributeMaxDynamicSharedMemorySize, SMEM_BYTES);

    // splitters
    split_kernel<<<2048, 256>>>(feat, fhi, fmid, (size_t)M_DIM * D_DIM / 4);
    dim3 tb(32, 8);
    split_wt_kernel<<<dim3(H_DIM / 32, D_DIM / 32), tb>>>(W0, whi + wo0, wmid + wo0, D_DIM, H_DIM);
    split_wt_kernel<<<dim3(H_DIM / 32, H_DIM / 32), tb>>>(W1, whi + wo1, wmid + wo1, H_DIM, H_DIM);
    split_wt_kernel<<<dim3(H_DIM / 32, H_DIM / 32), tb>>>(W2, whi + wo2, wmid + wo2, H_DIM, H_DIM);
    split_wt_kernel<<<dim3(H_DIM / 32, H_DIM / 32), tb>>>(W3, whi + wo3, wmid + wo3, H_DIM, H_DIM);

    dim3 grid(H_DIM / 128, M_DIM / 128);   // (8, 256)
    gemm_hmma<<<grid, 256, SMEM_BYTES>>>(fhi, fmid, whi + wo0, wmid + wo0, b0,
                                         ahi, amid, nullptr, nullptr, D_DIM, 0);
    gemm_hmma<<<grid, 256, SMEM_BYTES>>>(ahi, amid, whi + wo1, wmid + wo1, b1,
                                         ahi + AHALF, amid + AHALF, nullptr, nullptr, H_DIM, 0);
    gemm_hmma<<<grid, 256, SMEM_BYTES>>>(ahi + AHALF, amid + AHALF, whi + wo2, wmid + wo2, b2,
                                         ahi, amid, nullptr, nullptr, H_DIM, 0);
    gemm_hmma<<<grid, 256, SMEM_BYTES>>>(ahi, amid, whi + wo3, wmid + wo3, b3,
                                         nullptr, nullptr, Wo, part, H_DIM, 1);
    scan_kernel<<<2, 256>>>(reward, cont, part, bo, out);
}

// round 5
// speedup vs baseline: 1.3579x; 1.3579x over previous
#include <cuda_runtime.h>
#include <cuda_bf16.h>
#include <cstdint>
#include <math.h>

#define T_DIM 64
#define B_DIM 512
#define D_DIM 1536
#define H_DIM 1024
#define M_DIM 32768
#define DISCOUNT 0.997f
#define LAM 0.95f

#define W_TOTAL (D_DIM * H_DIM + 3 * H_DIM * H_DIM)

// ---- allocation-free scratch ----
__device__ __nv_bfloat16 g_fhi [(size_t)M_DIM * D_DIM];
__device__ __nv_bfloat16 g_fmid[(size_t)M_DIM * D_DIM];
__device__ __nv_bfloat16 g_ahi [2][(size_t)M_DIM * H_DIM];
__device__ __nv_bfloat16 g_amid[2][(size_t)M_DIM * H_DIM];
__device__ __nv_bfloat16 g_whi [W_TOTAL];
__device__ __nv_bfloat16 g_wmid[W_TOTAL];
__device__ float g_partial[32 * (size_t)M_DIM];

// ---- helpers ----
__device__ __forceinline__ float bf16_rn(float x) { return __bfloat162float(__float2bfloat16(x)); }
__device__ __forceinline__ uint32_t packbf(float lo, float hi) {
    uint32_t r;
    asm("cvt.rn.bf16x2.f32 %0, %1, %2;" : "=r"(r) : "f"(hi), "f"(lo));
    return r;
}
__device__ __forceinline__ float silu(float x) { return x / (1.0f + expf(-x)); }

__device__ __forceinline__ void mma16816(float* d, const uint32_t* a, const uint32_t* b) {
    asm volatile(
        "mma.sync.aligned.m16n8k16.row.col.f32.bf16.bf16.f32 "
        "{%0,%1,%2,%3}, {%4,%5,%6,%7}, {%8,%9}, {%0,%1,%2,%3};"
        : "+f"(d[0]), "+f"(d[1]), "+f"(d[2]), "+f"(d[3])
        : "r"(a[0]), "r"(a[1]), "r"(a[2]), "r"(a[3]), "r"(b[0]), "r"(b[1]));
}

// ---------------------------------------------------------------------------
// splitter: fp32 -> bf16 hi/mid planes (same flat layout)
// ---------------------------------------------------------------------------
__global__ void __launch_bounds__(256)
split_kernel(const float* __restrict__ src, __nv_bfloat16* __restrict__ hi,
             __nv_bfloat16* __restrict__ mid, size_t n4)
{
    size_t i = (size_t)blockIdx.x * blockDim.x + threadIdx.x;
    const size_t stride = (size_t)gridDim.x * blockDim.x;
    const float4* s4 = (const float4*)src;
    uint32_t* h2 = (uint32_t*)hi;
    uint32_t* m2 = (uint32_t*)mid;
    for (; i < n4; i += stride) {
        float4 v = s4[i];
        float hx = bf16_rn(v.x), hy = bf16_rn(v.y), hz = bf16_rn(v.z), hw = bf16_rn(v.w);
        h2[i * 2]     = packbf(hx, hy);
        h2[i * 2 + 1] = packbf(hz, hw);
        m2[i * 2]     = packbf(v.x - hx, v.y - hy);
        m2[i * 2 + 1] = packbf(v.z - hz, v.w - hw);
    }
}

// ---------------------------------------------------------------------------
// weight splitter + transpose: W[K,N] fp32 -> Wt_hi/Wt_mid [N,K] bf16
// ---------------------------------------------------------------------------
__global__ void __launch_bounds__(256)
split_wt_kernel(const float* __restrict__ W, __nv_bfloat16* __restrict__ whi,
                __nv_bfloat16* __restrict__ wmid, int K, int N)
{
    __shared__ float t[32][33];
    const int k0 = blockIdx.y * 32, n0 = blockIdx.x * 32;
    const int tx = threadIdx.x, ty = threadIdx.y;   // (32, 8)
    #pragma unroll
    for (int j = 0; j < 32; j += 8)
        t[ty + j][tx] = W[(size_t)(k0 + ty + j) * N + n0 + tx];
    __syncthreads();
    #pragma unroll
    for (int j = 0; j < 32; j += 8) {
        const float v = t[tx][ty + j];
        const float h = bf16_rn(v);
        const size_t o = (size_t)(n0 + ty + j) * K + k0 + tx;
        whi[o]  = __float2bfloat16(v);
        wmid[o] = __float2bfloat16(v - h);
    }
}

// ---------------------------------------------------------------------------
// GEMM: 128x128 tile, 8 warps (2m x 4n), LDG->reg->STS double buffer (R3
// structure), LDS.32 fragments on stride-40 layout, 3xBF16 split mma.sync.
// All operands pre-split bf16 planes; B pre-transposed [N,K].
// ---------------------------------------------------------------------------
#define STRIDE_H 40
#define TILE_BYTES (128 * STRIDE_H * 2)      // 10240
#define STAGE_BYTES (4 * TILE_BYTES)         // 40960: A_hi, A_mid, B_hi, B_mid
#define SMEM_BYTES (2 * STAGE_BYTES)         // 81920

__global__ void __launch_bounds__(256, 1)
gemm_hmma(const __nv_bfloat16* __restrict__ Ahi, const __nv_bfloat16* __restrict__ Amid,
          const __nv_bfloat16* __restrict__ Bhi, const __nv_bfloat16* __restrict__ Bmid,
          const float* __restrict__ bias,
          __nv_bfloat16* __restrict__ Chi, __nv_bfloat16* __restrict__ Cmid,
          const float* __restrict__ Wo, float* __restrict__ partial,
          int K, int mode)
{
    extern __shared__ char smem[];
    const int tid  = threadIdx.x;
    const int wid  = tid >> 5;
    const int lane = tid & 31;
    const int row0 = blockIdx.y * 128;
    const int col0 = blockIdx.x * 128;
    const int wm = wid & 1;       // 2 m-warps
    const int wn = wid >> 1;      // 4 n-warps

    // global load mapping: each thread owns one 128-elem row-half per plane
    const int r_ld = tid >> 1;              // 0..127 (row in A tile / col in B tile)
    const int seg  = (tid & 1) * 16;        // half offset within 32-elem chunk

    const __nv_bfloat16* pAh = Ahi  + (size_t)(row0 + r_ld) * K + seg;
    const __nv_bfloat16* pAm = Amid + (size_t)(row0 + r_ld) * K + seg;
    const __nv_bfloat16* pBh = Bhi  + (size_t)(col0 + r_ld) * K + seg;
    const __nv_bfloat16* pBm = Bmid + (size_t)(col0 + r_ld) * K + seg;

    // STS target (halves index -> byte)
    const uint32_t sts_off = (uint32_t)(r_ld * STRIDE_H + seg) * 2;

    float acc[4][4][4];
    #pragma unroll
    for (int i = 0; i < 4; i++)
        #pragma unroll
        for (int j = 0; j < 4; j++)
            #pragma unroll
            for (int c = 0; c < 4; c++) acc[i][j][c] = 0.0f;

    const int nk = K >> 5;   // 32 K-elems per chunk
    uint4 vAh[2], vAm[2], vBh[2], vBm[2];

    // ---- load chunk 0 ----
    vAh[0] = *(const uint4*)(pAh);     vAh[1] = *(const uint4*)(pAh + 8);
    vAm[0] = *(const uint4*)(pAm);     vAm[1] = *(const uint4*)(pAm + 8);
    vBh[0] = *(const uint4*)(pBh);     vBh[1] = *(const uint4*)(pBh + 8);
    vBm[0] = *(const uint4*)(pBm);     vBm[1] = *(const uint4*)(pBm + 8);

    auto do_sts = [&](int buf) {
        char* s = smem + buf * STAGE_BYTES;
        *(uint4*)(s + sts_off)                       = vAh[0];
        *(uint4*)(s + sts_off + 16)                  = vAh[1];
        *(uint4*)(s + TILE_BYTES + sts_off)          = vAm[0];
        *(uint4*)(s + TILE_BYTES + sts_off + 16)     = vAm[1];
        *(uint4*)(s + 2 * TILE_BYTES + sts_off)      = vBh[0];
        *(uint4*)(s + 2 * TILE_BYTES + sts_off + 16) = vBh[1];
        *(uint4*)(s + 3 * TILE_BYTES + sts_off)      = vBm[0];
        *(uint4*)(s + 3 * TILE_BYTES + sts_off + 16) = vBm[1];
    };

    do_sts(0);
    __syncthreads();

    for (int kt = 0; kt < nk; kt++) {
        const int buf = kt & 1;
        if (kt + 1 < nk) {
            const size_t ko = (size_t)(kt + 1) * 32;
            vAh[0] = *(const uint4*)(pAh + ko);  vAh[1] = *(const uint4*)(pAh + ko + 8);
            vAm[0] = *(const uint4*)(pAm + ko);  vAm[1] = *(const uint4*)(pAm + ko + 8);
            vBh[0] = *(const uint4*)(pBh + ko);  vBh[1] = *(const uint4*)(pBh + ko + 8);
            vBm[0] = *(const uint4*)(pBm + ko);  vBm[1] = *(const uint4*)(pBm + ko + 8);
        }

        const uint32_t* Ah = (const uint32_t*)(smem + buf * STAGE_BYTES);
        const uint32_t* Am = (const uint32_t*)(smem + buf * STAGE_BYTES + TILE_BYTES);
        const uint32_t* Bh = (const uint32_t*)(smem + buf * STAGE_BYTES + 2 * TILE_BYTES);
        const uint32_t* Bm = (const uint32_t*)(smem + buf * STAGE_BYTES + 3 * TILE_BYTES);

        #pragma unroll
        for (int ks = 0; ks < 2; ks++) {
            uint32_t a[4][2][4], b[4][2][2];
            const int kcol = ks * 8 + (lane & 3);
            #pragma unroll
            for (int mi = 0; mi < 4; mi++) {
                const int r = wm * 64 + mi * 16 + (lane >> 2);
                const int i00 = r * (STRIDE_H / 2) + kcol;
                const int i10 = (r + 8) * (STRIDE_H / 2) + kcol;
                a[mi][0][0] = Ah[i00]; a[mi][0][1] = Ah[i10];
                a[mi][0][2] = Ah[i00 + 4]; a[mi][0][3] = Ah[i10 + 4];
                a[mi][1][0] = Am[i00]; a[mi][1][1] = Am[i10];
                a[mi][1][2] = Am[i00 + 4]; a[mi][1][3] = Am[i10 + 4];
            }
            #pragma unroll
            for (int ni = 0; ni < 4; ni++) {
                const int n = wn * 32 + ni * 8 + (lane >> 2);
                const int i0 = n * (STRIDE_H / 2) + kcol;
                b[ni][0][0] = Bh[i0]; b[ni][0][1] = Bh[i0 + 4];
                b[ni][1][0] = Bm[i0]; b[ni][1][1] = Bm[i0 + 4];
            }
            #pragma unroll
            for (int mi = 0; mi < 4; mi++)
                #pragma unroll
                for (int ni = 0; ni < 4; ni++) {
                    mma16816(acc[mi][ni], a[mi][0], b[ni][0]);  // hi*hi
                    mma16816(acc[mi][ni], a[mi][0], b[ni][1]);  // hi*mid
                    mma16816(acc[mi][ni], a[mi][1], b[ni][0]);  // mid*hi
                }
        }

        if (kt + 1 < nk) {
            do_sts(buf ^ 1);
            __syncthreads();
        }
    }

    // ---- epilogue ----
    if (mode == 0) {
        #pragma unroll
        for (int mi = 0; mi < 4; mi++) {
            const int grow = row0 + wm * 64 + mi * 16 + (lane >> 2);
            #pragma unroll
            for (int ni = 0; ni < 4; ni++) {
                const int gcol = col0 + wn * 32 + ni * 8 + (lane & 3) * 2;
                const float b0 = bias[gcol], b1 = bias[gcol + 1];
                float x0 = silu(acc[mi][ni][0] + b0);
                float x1 = silu(acc[mi][ni][1] + b1);
                float x2 = silu(acc[mi][ni][2] + b0);
                float x3 = silu(acc[mi][ni][3] + b1);
                float h0 = bf16_rn(x0), h1 = bf16_rn(x1), h2 = bf16_rn(x2), h3 = bf16_rn(x3);
                const size_t o0 = (size_t)grow * H_DIM + gcol;
                const size_t o1 = (size_t)(grow + 8) * H_DIM + gcol;
                *(uint32_t*)(Chi  + o0) = packbf(h0, h1);
                *(uint32_t*)(Cmid + o0) = packbf(x0 - h0, x1 - h1);
                *(uint32_t*)(Chi  + o1) = packbf(h2, h3);
                *(uint32_t*)(Cmid + o1) = packbf(x2 - h2, x3 - h3);
            }
        }
    } else {
        const int p = blockIdx.x * 4 + wn;
        #pragma unroll
        for (int mi = 0; mi < 4; mi++) {
            float s0 = 0.0f, s1 = 0.0f;
            #pragma unroll
            for (int ni = 0; ni < 4; ni++) {
                const int gcol = col0 + wn * 32 + ni * 8 + (lane & 3) * 2;
                const float b0 = bias[gcol], b1 = bias[gcol + 1];
                const float w0 = Wo[gcol], w1 = Wo[gcol + 1];
                s0 += silu(acc[mi][ni][0] + b0) * w0 + silu(acc[mi][ni][1] + b1) * w1;
                s1 += silu(acc[mi][ni][2] + b0) * w0 + silu(acc[mi][ni][3] + b1) * w1;
            }
            s0 += __shfl_xor_sync(0xffffffffu, s0, 1);
            s0 += __shfl_xor_sync(0xffffffffu, s0, 2);
            s1 += __shfl_xor_sync(0xffffffffu, s1, 1);
            s1 += __shfl_xor_sync(0xffffffffu, s1, 2);
            if ((lane & 3) == 0) {
                const int r = row0 + wm * 64 + mi * 16 + (lane >> 2);
                partial[(size_t)p * M_DIM + r]     = s0;
                partial[(size_t)p * M_DIM + r + 8] = s1;
            }
        }
    }
}

// ---------------------------------------------------------------------------
// GAE reverse scan; value[m] = sum of 32 partials + bo.
// ---------------------------------------------------------------------------
__global__ void __launch_bounds__(256)
scan_kernel(const float* __restrict__ reward, const float* __restrict__ cont,
            const float* __restrict__ partial, const float* __restrict__ bo,
            float* __restrict__ out)
{
    const int b = blockIdx.x * blockDim.x + threadIdx.x;
    if (b >= B_DIM) return;
    const float bov = bo[0];

    auto val = [&](int m) {
        float s = 0.0f;
        #pragma unroll
        for (int c = 0; c < 32; c++) s += partial[(size_t)c * M_DIM + m];
        return s + bov;
    };

    float adv = 0.0f;
    float v_next = val((T_DIM - 1) * B_DIM + b);
    for (int t = T_DIM - 2; t >= 0; t--) {
        const float v0   = val(t * B_DIM + b);
        const float disc = cont[(t + 1) * B_DIM + b] * DISCOUNT;
        const float dl   = disc * LAM;
        const float delta = reward[t * B_DIM + b] + disc * v_next - v0;
        adv = delta + dl * adv;
        out[t * B_DIM + b] = adv + v0;                       // ret
        out[(T_DIM - 1) * B_DIM + t * B_DIM + b] = v0;       // baseline
        v_next = v0;
    }
}

// ---------------------------------------------------------------------------
extern "C" void kernel_launch(void* const* d_in, const int* in_sizes, int n_in,
                              void* d_out, int out_size)
{
    const float* feat   = (const float*)d_in[0];
    const float* reward = (const float*)d_in[1];
    const float* cont   = (const float*)d_in[2];
    const float* W0 = (const float*)d_in[3];
    const float* b0 = (const float*)d_in[4];
    const float* W1 = (const float*)d_in[5];
    const float* b1 = (const float*)d_in[6];
    const float* W2 = (const float*)d_in[7];
    const float* b2 = (const float*)d_in[8];
    const float* W3 = (const float*)d_in[9];
    const float* b3 = (const float*)d_in[10];
    const float* Wo = (const float*)d_in[11];
    const float* bo = (const float*)d_in[12];
    float* out = (float*)d_out;

    __nv_bfloat16 *fhi, *fmid, *ahi, *amid, *whi, *wmid;
    float *part;
    cudaGetSymbolAddress((void**)&fhi,  g_fhi);
    cudaGetSymbolAddress((void**)&fmid, g_fmid);
    cudaGetSymbolAddress((void**)&ahi,  g_ahi);
    cudaGetSymbolAddress((void**)&amid, g_amid);
    cudaGetSymbolAddress((void**)&whi,  g_whi);
    cudaGetSymbolAddress((void**)&wmid, g_wmid);
    cudaGetSymbolAddress((void**)&part, g_partial);

    const size_t AHALF = (size_t)M_DIM * H_DIM;
    const size_t wo0 = 0;
    const size_t wo1 = (size_t)D_DIM * H_DIM;
    const size_t wo2 = wo1 + (size_t)H_DIM * H_DIM;
    const size_t wo3 = wo2 + (size_t)H_DIM * H_DIM;

    cudaFuncSetAttribute(gemm_hmma, cudaFuncAttributeMaxDynamicSharedMemorySize, SMEM_BYTES);

    // splitters
    split_kernel<<<2048, 256>>>(feat, fhi, fmid, (size_t)M_DIM * D_DIM / 4);
    dim3 tb(32, 8);
    split_wt_kernel<<<dim3(H_DIM / 32, D_DIM / 32), tb>>>(W0, whi + wo0, wmid + wo0, D_DIM, H_DIM);
    split_wt_kernel<<<dim3(H_DIM / 32, H_DIM / 32), tb>>>(W1, whi + wo1, wmid + wo1, H_DIM, H_DIM);
    split_wt_kernel<<<dim3(H_DIM / 32, H_DIM / 32), tb>>>(W2, whi + wo2, wmid + wo2, H_DIM, H_DIM);
    split_wt_kernel<<<dim3(H_DIM / 32, H_DIM / 32), tb>>>(W3, whi + wo3, wmid + wo3, H_DIM, H_DIM);

    dim3 grid(H_DIM / 128, M_DIM / 128);   // (8, 256)
    gemm_hmma<<<grid, 256, SMEM_BYTES>>>(fhi, fmid, whi + wo0, wmid + wo0, b0,
                                         ahi, amid, nullptr, nullptr, D_DIM, 0);
    gemm_hmma<<<grid, 256, SMEM_BYTES>>>(ahi, amid, whi + wo1, wmid + wo1, b1,
                                         ahi + AHALF, amid + AHALF, nullptr, nullptr, H_DIM, 0);
    gemm_hmma<<<grid, 256, SMEM_BYTES>>>(ahi + AHALF, amid + AHALF, whi + wo2, wmid + wo2, b2,
                                         ahi, amid, nullptr, nullptr, H_DIM, 0);
    gemm_hmma<<<grid, 256, SMEM_BYTES>>>(ahi, amid, whi + wo3, wmid + wo3, b3,
                                         nullptr, nullptr, Wo, part, H_DIM, 1);
    scan_kernel<<<2, 256>>>(reward, cont, part, bo, out);
}

// round 6
// speedup vs baseline: 1.5130x; 1.1142x over previous
#include <cuda_runtime.h>
#include <cuda_bf16.h>
#include <cstdint>
#include <math.h>

#define T_DIM 64
#define B_DIM 512
#define D_DIM 1536
#define H_DIM 1024
#define M_DIM 32768
#define DISCOUNT 0.997f
#define LAM 0.95f

#define W_TOTAL (D_DIM * H_DIM + 3 * H_DIM * H_DIM)

// ---- allocation-free scratch ----
__device__ __nv_bfloat16 g_fhi [(size_t)M_DIM * D_DIM];
__device__ __nv_bfloat16 g_fmid[(size_t)M_DIM * D_DIM];
__device__ __nv_bfloat16 g_ahi [2][(size_t)M_DIM * H_DIM];
__device__ __nv_bfloat16 g_amid[2][(size_t)M_DIM * H_DIM];
__device__ __nv_bfloat16 g_whi [W_TOTAL];
__device__ __nv_bfloat16 g_wmid[W_TOTAL];
__device__ float g_partial[32 * (size_t)M_DIM];

// ---- helpers ----
__device__ __forceinline__ uint32_t smem_to_u32(const void* p) {
    uint32_t a;
    asm("{ .reg .u64 t; cvta.to.shared.u64 t, %1; cvt.u32.u64 %0, t; }" : "=r"(a) : "l"(p));
    return a;
}
__device__ __forceinline__ float bf16_rn(float x) { return __bfloat162float(__float2bfloat16(x)); }
__device__ __forceinline__ uint32_t packbf(float lo, float hi) {
    uint32_t r;
    asm("cvt.rn.bf16x2.f32 %0, %1, %2;" : "=r"(r) : "f"(hi), "f"(lo));
    return r;
}
__device__ __forceinline__ float silu(float x) { return x / (1.0f + expf(-x)); }

__device__ __forceinline__ void mma16816(float* d, const uint32_t* a, const uint32_t* b) {
    asm volatile(
        "mma.sync.aligned.m16n8k16.row.col.f32.bf16.bf16.f32 "
        "{%0,%1,%2,%3}, {%4,%5,%6,%7}, {%8,%9}, {%0,%1,%2,%3};"
        : "+f"(d[0]), "+f"(d[1]), "+f"(d[2]), "+f"(d[3])
        : "r"(a[0]), "r"(a[1]), "r"(a[2]), "r"(a[3]), "r"(b[0]), "r"(b[1]));
}
#define CP16(dst, src) \
    asm volatile("cp.async.cg.shared.global [%0], [%1], 16;" :: "r"(dst), "l"(src))
#define CP_COMMIT asm volatile("cp.async.commit_group;" ::: "memory")
#define CP_WAIT0  asm volatile("cp.async.wait_group 0;" ::: "memory")

// ---------------------------------------------------------------------------
// splitter: fp32 -> bf16 hi/mid planes (same flat layout)
// ---------------------------------------------------------------------------
__global__ void __launch_bounds__(256)
split_kernel(const float* __restrict__ src, __nv_bfloat16* __restrict__ hi,
             __nv_bfloat16* __restrict__ mid, size_t n4)
{
    size_t i = (size_t)blockIdx.x * blockDim.x + threadIdx.x;
    const size_t stride = (size_t)gridDim.x * blockDim.x;
    const float4* s4 = (const float4*)src;
    uint32_t* h2 = (uint32_t*)hi;
    uint32_t* m2 = (uint32_t*)mid;
    for (; i < n4; i += stride) {
        float4 v = s4[i];
        float hx = bf16_rn(v.x), hy = bf16_rn(v.y), hz = bf16_rn(v.z), hw = bf16_rn(v.w);
        h2[i * 2]     = packbf(hx, hy);
        h2[i * 2 + 1] = packbf(hz, hw);
        m2[i * 2]     = packbf(v.x - hx, v.y - hy);
        m2[i * 2 + 1] = packbf(v.z - hz, v.w - hw);
    }
}

// ---------------------------------------------------------------------------
// weight splitter + transpose: W[K,N] fp32 -> Wt_hi/Wt_mid [N,K] bf16
// ---------------------------------------------------------------------------
__global__ void __launch_bounds__(256)
split_wt_kernel(const float* __restrict__ W, __nv_bfloat16* __restrict__ whi,
                __nv_bfloat16* __restrict__ wmid, int K, int N)
{
    __shared__ float t[32][33];
    const int k0 = blockIdx.y * 32, n0 = blockIdx.x * 32;
    const int tx = threadIdx.x, ty = threadIdx.y;   // (32, 8)
    #pragma unroll
    for (int j = 0; j < 32; j += 8)
        t[ty + j][tx] = W[(size_t)(k0 + ty + j) * N + n0 + tx];
    __syncthreads();
    #pragma unroll
    for (int j = 0; j < 32; j += 8) {
        const float v = t[tx][ty + j];
        const float h = bf16_rn(v);
        const size_t o = (size_t)(n0 + ty + j) * K + k0 + tx;
        whi[o]  = __float2bfloat16(v);
        wmid[o] = __float2bfloat16(v - h);
    }
}

// ---------------------------------------------------------------------------
// GEMM: 128x128 tile, 8 warps (2m x 4n), cp.async 2-stage (single sync/iter),
// stride-40 smem + LDS.32 fragments (proven R3 pattern), 3xBF16 split mma.
// __launch_bounds__(256, 2) -> 2 CTAs/SM.
// ---------------------------------------------------------------------------
#define STRIDE_H 40
#define TILE_BYTES (128 * STRIDE_H * 2)      // 10240
#define STAGE_BYTES (4 * TILE_BYTES)         // 40960: A_hi, A_mid, B_hi, B_mid
#define SMEM_BYTES (2 * STAGE_BYTES)         // 81920

__global__ void __launch_bounds__(256, 2)
gemm_hmma(const __nv_bfloat16* __restrict__ Ahi, const __nv_bfloat16* __restrict__ Amid,
          const __nv_bfloat16* __restrict__ Bhi, const __nv_bfloat16* __restrict__ Bmid,
          const float* __restrict__ bias,
          __nv_bfloat16* __restrict__ Chi, __nv_bfloat16* __restrict__ Cmid,
          const float* __restrict__ Wo, float* __restrict__ partial,
          int K, int mode)
{
    extern __shared__ char smem[];
    const uint32_t sb = smem_to_u32(smem);
    const int tid  = threadIdx.x;
    const int wid  = tid >> 5;
    const int lane = tid & 31;
    const int row0 = blockIdx.y * 128;
    const int col0 = blockIdx.x * 128;
    const int wm = wid & 1;       // 2 m-warps
    const int wn = wid >> 1;      // 4 n-warps

    // gmem->smem mapping: each thread owns 32B (16 halves) of one row per plane
    const int r_ld = tid >> 1;              // 0..127
    const int seg  = (tid & 1) * 16;        // halves offset within 32-elem chunk

    const __nv_bfloat16* pAh = Ahi  + (size_t)(row0 + r_ld) * K + seg;
    const __nv_bfloat16* pAm = Amid + (size_t)(row0 + r_ld) * K + seg;
    const __nv_bfloat16* pBh = Bhi  + (size_t)(col0 + r_ld) * K + seg;
    const __nv_bfloat16* pBm = Bmid + (size_t)(col0 + r_ld) * K + seg;

    const uint32_t sts_off = (uint32_t)(r_ld * STRIDE_H + seg) * 2;

    float acc[4][4][4];
    #pragma unroll
    for (int i = 0; i < 4; i++)
        #pragma unroll
        for (int j = 0; j < 4; j++)
            #pragma unroll
            for (int c = 0; c < 4; c++) acc[i][j][c] = 0.0f;

    const int nk = K >> 5;   // 32 K-halves per chunk

    auto issue = [&](int kt) {
        const uint32_t base = sb + (kt & 1) * STAGE_BYTES + sts_off;
        const size_t ko = (size_t)kt * 32;
        CP16(base,                       pAh + ko); CP16(base + 16,                  pAh + ko + 8);
        CP16(base + TILE_BYTES,          pAm + ko); CP16(base + TILE_BYTES + 16,     pAm + ko + 8);
        CP16(base + 2 * TILE_BYTES,      pBh + ko); CP16(base + 2 * TILE_BYTES + 16, pBh + ko + 8);
        CP16(base + 3 * TILE_BYTES,      pBm + ko); CP16(base + 3 * TILE_BYTES + 16, pBm + ko + 8);
    };

    issue(0); CP_COMMIT;

    for (int kt = 0; kt < nk; kt++) {
        CP_WAIT0;              // stage kt resident
        __syncthreads();       // all warps done with buffer (kt+1)&1 from iter kt-1
        if (kt + 1 < nk) { issue(kt + 1); CP_COMMIT; }   // overlaps compute below

        const int buf = kt & 1;
        const uint32_t* Ah = (const uint32_t*)(smem + buf * STAGE_BYTES);
        const uint32_t* Am = (const uint32_t*)(smem + buf * STAGE_BYTES + TILE_BYTES);
        const uint32_t* Bh = (const uint32_t*)(smem + buf * STAGE_BYTES + 2 * TILE_BYTES);
        const uint32_t* Bm = (const uint32_t*)(smem + buf * STAGE_BYTES + 3 * TILE_BYTES);

        #pragma unroll
        for (int ks = 0; ks < 2; ks++) {
            const int kcol = ks * 8 + (lane & 3);
            uint32_t b[4][2][2];
            #pragma unroll
            for (int ni = 0; ni < 4; ni++) {
                const int n = wn * 32 + ni * 8 + (lane >> 2);
                const int i0 = n * (STRIDE_H / 2) + kcol;
                b[ni][0][0] = Bh[i0]; b[ni][0][1] = Bh[i0 + 4];
                b[ni][1][0] = Bm[i0]; b[ni][1][1] = Bm[i0 + 4];
            }
            #pragma unroll
            for (int mi = 0; mi < 4; mi++) {
                const int r = wm * 64 + mi * 16 + (lane >> 2);
                const int i00 = r * (STRIDE_H / 2) + kcol;
                const int i10 = (r + 8) * (STRIDE_H / 2) + kcol;
                uint32_t a[2][4];
                a[0][0] = Ah[i00]; a[0][1] = Ah[i10];
                a[0][2] = Ah[i00 + 4]; a[0][3] = Ah[i10 + 4];
                a[1][0] = Am[i00]; a[1][1] = Am[i10];
                a[1][2] = Am[i00 + 4]; a[1][3] = Am[i10 + 4];
                #pragma unroll
                for (int ni = 0; ni < 4; ni++) {
                    mma16816(acc[mi][ni], a[0], b[ni][0]);  // hi*hi
                    mma16816(acc[mi][ni], a[0], b[ni][1]);  // hi*mid
                    mma16816(acc[mi][ni], a[1], b[ni][0]);  // mid*hi
                }
            }
        }
    }

    // ---- epilogue ----
    if (mode == 0) {
        #pragma unroll
        for (int mi = 0; mi < 4; mi++) {
            const int grow = row0 + wm * 64 + mi * 16 + (lane >> 2);
            #pragma unroll
            for (int ni = 0; ni < 4; ni++) {
                const int gcol = col0 + wn * 32 + ni * 8 + (lane & 3) * 2;
                const float b0 = bias[gcol], b1 = bias[gcol + 1];
                float x0 = silu(acc[mi][ni][0] + b0);
                float x1 = silu(acc[mi][ni][1] + b1);
                float x2 = silu(acc[mi][ni][2] + b0);
                float x3 = silu(acc[mi][ni][3] + b1);
                float h0 = bf16_rn(x0), h1 = bf16_rn(x1), h2 = bf16_rn(x2), h3 = bf16_rn(x3);
                const size_t o0 = (size_t)grow * H_DIM + gcol;
                const size_t o1 = (size_t)(grow + 8) * H_DIM + gcol;
                *(uint32_t*)(Chi  + o0) = packbf(h0, h1);
                *(uint32_t*)(Cmid + o0) = packbf(x0 - h0, x1 - h1);
                *(uint32_t*)(Chi  + o1) = packbf(h2, h3);
                *(uint32_t*)(Cmid + o1) = packbf(x2 - h2, x3 - h3);
            }
        }
    } else {
        const int p = blockIdx.x * 4 + wn;
        #pragma unroll
        for (int mi = 0; mi < 4; mi++) {
            float s0 = 0.0f, s1 = 0.0f;
            #pragma unroll
            for (int ni = 0; ni < 4; ni++) {
                const int gcol = col0 + wn * 32 + ni * 8 + (lane & 3) * 2;
                const float b0 = bias[gcol], b1 = bias[gcol + 1];
                const float w0 = Wo[gcol], w1 = Wo[gcol + 1];
                s0 += silu(acc[mi][ni][0] + b0) * w0 + silu(acc[mi][ni][1] + b1) * w1;
                s1 += silu(acc[mi][ni][2] + b0) * w0 + silu(acc[mi][ni][3] + b1) * w1;
            }
            s0 += __shfl_xor_sync(0xffffffffu, s0, 1);
            s0 += __shfl_xor_sync(0xffffffffu, s0, 2);
            s1 += __shfl_xor_sync(0xffffffffu, s1, 1);
            s1 += __shfl_xor_sync(0xffffffffu, s1, 2);
            if ((lane & 3) == 0) {
                const int r = row0 + wm * 64 + mi * 16 + (lane >> 2);
                partial[(size_t)p * M_DIM + r]     = s0;
                partial[(size_t)p * M_DIM + r + 8] = s1;
            }
        }
    }
}

// ---------------------------------------------------------------------------
// GAE reverse scan; value[m] = sum of 32 partials + bo.
// ---------------------------------------------------------------------------
__global__ void __launch_bounds__(256)
scan_kernel(const float* __restrict__ reward, const float* __restrict__ cont,
            const float* __restrict__ partial, const float* __restrict__ bo,
            float* __restrict__ out)
{
    const int b = blockIdx.x * blockDim.x + threadIdx.x;
    if (b >= B_DIM) return;
    const float bov = bo[0];

    auto val = [&](int m) {
        float s = 0.0f;
        #pragma unroll
        for (int c = 0; c < 32; c++) s += partial[(size_t)c * M_DIM + m];
        return s + bov;
    };

    float adv = 0.0f;
    float v_next = val((T_DIM - 1) * B_DIM + b);
    for (int t = T_DIM - 2; t >= 0; t--) {
        const float v0   = val(t * B_DIM + b);
        const float disc = cont[(t + 1) * B_DIM + b] * DISCOUNT;
        const float dl   = disc * LAM;
        const float delta = reward[t * B_DIM + b] + disc * v_next - v0;
        adv = delta + dl * adv;
        out[t * B_DIM + b] = adv + v0;                       // ret
        out[(T_DIM - 1) * B_DIM + t * B_DIM + b] = v0;       // baseline
        v_next = v0;
    }
}

// ---------------------------------------------------------------------------
extern "C" void kernel_launch(void* const* d_in, const int* in_sizes, int n_in,
                              void* d_out, int out_size)
{
    const float* feat   = (const float*)d_in[0];
    const float* reward = (const float*)d_in[1];
    const float* cont   = (const float*)d_in[2];
    const float* W0 = (const float*)d_in[3];
    const float* b0 = (const float*)d_in[4];
    const float* W1 = (const float*)d_in[5];
    const float* b1 = (const float*)d_in[6];
    const float* W2 = (const float*)d_in[7];
    const float* b2 = (const float*)d_in[8];
    const float* W3 = (const float*)d_in[9];
    const float* b3 = (const float*)d_in[10];
    const float* Wo = (const float*)d_in[11];
    const float* bo = (const float*)d_in[12];
    float* out = (float*)d_out;

    __nv_bfloat16 *fhi, *fmid, *ahi, *amid, *whi, *wmid;
    float *part;
    cudaGetSymbolAddress((void**)&fhi,  g_fhi);
    cudaGetSymbolAddress((void**)&fmid, g_fmid);
    cudaGetSymbolAddress((void**)&ahi,  g_ahi);
    cudaGetSymbolAddress((void**)&amid, g_amid);
    cudaGetSymbolAddress((void**)&whi,  g_whi);
    cudaGetSymbolAddress((void**)&wmid, g_wmid);
    cudaGetSymbolAddress((void**)&part, g_partial);

    const size_t AHALF = (size_t)M_DIM * H_DIM;
    const size_t wo0 = 0;
    const size_t wo1 = (size_t)D_DIM * H_DIM;
    const size_t wo2 = wo1 + (size_t)H_DIM * H_DIM;
    const size_t wo3 = wo2 + (size_t)H_DIM * H_DIM;

    cudaFuncSetAttribute(gemm_hmma, cudaFuncAttributeMaxDynamicSharedMemorySize, SMEM_BYTES);

    // splitters
    split_kernel<<<2048, 256>>>(feat, fhi, fmid, (size_t)M_DIM * D_DIM / 4);
    dim3 tb(32, 8);
    split_wt_kernel<<<dim3(H_DIM / 32, D_DIM / 32), tb>>>(W0, whi + wo0, wmid + wo0, D_DIM, H_DIM);
    split_wt_kernel<<<dim3(H_DIM / 32, H_DIM / 32), tb>>>(W1, whi + wo1, wmid + wo1, H_DIM, H_DIM);
    split_wt_kernel<<<dim3(H_DIM / 32, H_DIM / 32), tb>>>(W2, whi + wo2, wmid + wo2, H_DIM, H_DIM);
    split_wt_kernel<<<dim3(H_DIM / 32, H_DIM / 32), tb>>>(W3, whi + wo3, wmid + wo3, H_DIM, H_DIM);

    dim3 grid(H_DIM / 128, M_DIM / 128);   // (8, 256)
    gemm_hmma<<<grid, 256, SMEM_BYTES>>>(fhi, fmid, whi + wo0, wmid + wo0, b0,
                                         ahi, amid, nullptr, nullptr, D_DIM, 0);
    gemm_hmma<<<grid, 256, SMEM_BYTES>>>(ahi, amid, whi + wo1, wmid + wo1, b1,
                                         ahi + AHALF, amid + AHALF, nullptr, nullptr, H_DIM, 0);
    gemm_hmma<<<grid, 256, SMEM_BYTES>>>(ahi + AHALF, amid + AHALF, whi + wo2, wmid + wo2, b2,
                                         ahi, amid, nullptr, nullptr, H_DIM, 0);
    gemm_hmma<<<grid, 256, SMEM_BYTES>>>(ahi, amid, whi + wo3, wmid + wo3, b3,
                                         nullptr, nullptr, Wo, part, H_DIM, 1);
    scan_kernel<<<2, 256>>>(reward, cont, part, bo, out);
}

// round 7
// speedup vs baseline: 1.6160x; 1.0681x over previous
#include <cuda_runtime.h>
#include <cuda_bf16.h>
#include <cstdint>
#include <math.h>

#define T_DIM 64
#define B_DIM 512
#define D_DIM 1536
#define H_DIM 1024
#define M_DIM (T_DIM * B_DIM)   // 32768
#define DISCOUNT 0.997f
#define LAM 0.95f

// Scratch (allocation-free)
__device__ float g_buf0[(size_t)M_DIM * H_DIM];
__device__ float g_buf1[(size_t)M_DIM * H_DIM];
__device__ float g_partial[32 * (size_t)M_DIM];

// ---------------------------------------------------------------------------
// smem: 4 tiles per stage (A_hi, A_mid, B_hi, B_mid), each [128][40] bf16.
// Stride 40 halves (80 B): scalar LDS conflict-free AND ldmatrix conflict-free
// (8 rows at 80B stride tile all 32 banks exactly once).
// ---------------------------------------------------------------------------
#define STRIDE_H 40
#define TILE_BYTES (128 * STRIDE_H * 2)      // 10240
#define STAGE_BYTES (4 * TILE_BYTES)         // 40960
#define SMEM_BYTES (2 * STAGE_BYTES)         // 81920

__device__ __forceinline__ uint32_t smem_to_u32(const void* p) {
    uint32_t a;
    asm("{ .reg .u64 t; cvta.to.shared.u64 t, %1; cvt.u32.u64 %0, t; }" : "=r"(a) : "l"(p));
    return a;
}
__device__ __forceinline__ float bf16_rn(float x) {
    return __bfloat162float(__float2bfloat16(x));
}
__device__ __forceinline__ uint32_t packbf(float lo, float hi) {
    uint32_t r;
    asm("cvt.rn.bf16x2.f32 %0, %1, %2;" : "=r"(r) : "f"(hi), "f"(lo));
    return r;
}
__device__ __forceinline__ float silu(float x) { return x / (1.0f + expf(-x)); }

__device__ __forceinline__ void mma16816(float* d, const uint32_t* a, const uint32_t* b) {
    asm volatile(
        "mma.sync.aligned.m16n8k16.row.col.f32.bf16.bf16.f32 "
        "{%0,%1,%2,%3}, {%4,%5,%6,%7}, {%8,%9}, {%0,%1,%2,%3};"
        : "+f"(d[0]), "+f"(d[1]), "+f"(d[2]), "+f"(d[3])
        : "r"(a[0]), "r"(a[1]), "r"(a[2]), "r"(a[3]), "r"(b[0]), "r"(b[1]));
}
#define LDSM4(r, addr) \
    asm volatile("ldmatrix.sync.aligned.m8n8.x4.shared.b16 {%0,%1,%2,%3}, [%4];" \
        : "=r"((r)[0]), "=r"((r)[1]), "=r"((r)[2]), "=r"((r)[3]) : "r"(addr))

// ---------------------------------------------------------------------------
// C[M,1024] = silu(A[M,K] @ W[K,1024] + bias)  via 3xBF16 split mma.sync.
// R3 mainloop structure (LDG->reg->split->STS double buffer), ldmatrix frags.
// mode 0: write activations. mode 1: fused value head -> g_partial.
// ---------------------------------------------------------------------------
__global__ void __launch_bounds__(256, 1)
gemm_hmma(const float* __restrict__ A, const float* __restrict__ W,
          const float* __restrict__ bias, float* __restrict__ C,
          const float* __restrict__ Wo, float* __restrict__ partial,
          int K, int mode)
{
    extern __shared__ char smem[];
    const uint32_t sbu = smem_to_u32(smem);
    const int tid  = threadIdx.x;
    const int wid  = tid >> 5;
    const int lane = tid & 31;
    const int row0 = blockIdx.y * 128;
    const int col0 = blockIdx.x * 128;

    // warp layout: 2 (m) x 4 (n); warp tile 64 x 32
    const int wm = wid & 1;
    const int wn = wid >> 1;

    // global load mappings (identical to R3)
    const int m_a  = tid >> 3;            // A row 0..31 (+32*it)
    const int kc_a = (tid & 7) * 4;       // A k-float 0..28
    const int n_b  = tid & 127;           // B col
    const int kg_b = (tid >> 7) * 4;      // B k base {0,4} (+8*it, +j)

    const float* Aptr = A + (size_t)(row0 + m_a) * K + kc_a;
    const float* Wptr = W + (size_t)kg_b * H_DIM + col0 + n_b;

    float acc[4][4][4];
    #pragma unroll
    for (int i = 0; i < 4; i++)
        #pragma unroll
        for (int j = 0; j < 4; j++)
            #pragma unroll
            for (int c = 0; c < 4; c++) acc[i][j][c] = 0.0f;

    const int nk = K >> 5;
    float4 av[4];
    float  bw[4][4];

    // ---- load chunk 0 ----
    #pragma unroll
    for (int it = 0; it < 4; it++)
        av[it] = *(const float4*)(Aptr + (size_t)(32 * it) * K);
    #pragma unroll
    for (int it = 0; it < 4; it++)
        #pragma unroll
        for (int j = 0; j < 4; j++)
            bw[it][j] = Wptr[(size_t)(8 * it + j) * H_DIM];

    auto do_sts = [&](int buf) {
        uint32_t* Ah = (uint32_t*)(smem + buf * STAGE_BYTES);
        uint32_t* Am = (uint32_t*)(smem + buf * STAGE_BYTES + TILE_BYTES);
        uint32_t* Bh = (uint32_t*)(smem + buf * STAGE_BYTES + 2 * TILE_BYTES);
        uint32_t* Bm = (uint32_t*)(smem + buf * STAGE_BYTES + 3 * TILE_BYTES);
        #pragma unroll
        for (int it = 0; it < 4; it++) {
            const int idx = ((m_a + 32 * it) * STRIDE_H + kc_a) >> 1;  // uint32 units
            float hx = bf16_rn(av[it].x), hy = bf16_rn(av[it].y);
            float hz = bf16_rn(av[it].z), hw = bf16_rn(av[it].w);
            Ah[idx]     = packbf(hx, hy);
            Ah[idx + 1] = packbf(hz, hw);
            Am[idx]     = packbf(av[it].x - hx, av[it].y - hy);
            Am[idx + 1] = packbf(av[it].z - hz, av[it].w - hw);
        }
        #pragma unroll
        for (int it = 0; it < 4; it++) {
            const int idx = (n_b * STRIDE_H + kg_b + 8 * it) >> 1;
            float h0 = bf16_rn(bw[it][0]), h1 = bf16_rn(bw[it][1]);
            float h2 = bf16_rn(bw[it][2]), h3 = bf16_rn(bw[it][3]);
            Bh[idx]     = packbf(h0, h1);
            Bh[idx + 1] = packbf(h2, h3);
            Bm[idx]     = packbf(bw[it][0] - h0, bw[it][1] - h1);
            Bm[idx + 1] = packbf(bw[it][2] - h2, bw[it][3] - h3);
        }
    };

    do_sts(0);
    __syncthreads();

    // ldmatrix per-lane address components (bytes, relative to plane base)
    const int lm = lane >> 3;    // matrix index 0..3
    const int lr = lane & 7;     // row within matrix
    // A: row = wm*64 + mi*16 + (lm&1)*8 + lr ; k-halves seg = ks*16 + (lm>>1)*8
    const uint32_t a_lane = (uint32_t)((wm * 64 + (lm & 1) * 8 + lr) * (STRIDE_H * 2)
                                       + ((lm >> 1) * 8) * 2);
    // B: n = wn*32 + pair*16 + (lm>>1)*8 + lr ; k seg = ks*16 + (lm&1)*8
    const uint32_t b_lane = (uint32_t)((wn * 32 + (lm >> 1) * 8 + lr) * (STRIDE_H * 2)
                                       + ((lm & 1) * 8) * 2);

    for (int kt = 0; kt < nk; kt++) {
        const int buf = kt & 1;
        // prefetch next chunk into registers
        if (kt + 1 < nk) {
            #pragma unroll
            for (int it = 0; it < 4; it++)
                av[it] = *(const float4*)(Aptr + (size_t)(32 * it) * K + (kt + 1) * 32);
            #pragma unroll
            for (int it = 0; it < 4; it++)
                #pragma unroll
                for (int j = 0; j < 4; j++)
                    bw[it][j] = Wptr[(size_t)((kt + 1) * 32 + 8 * it + j) * H_DIM];
        }

        const uint32_t base = sbu + buf * STAGE_BYTES;

        #pragma unroll
        for (int ks = 0; ks < 2; ks++) {
            const uint32_t ko = (uint32_t)(ks * 32);   // 16 halves = 32 bytes
            uint32_t afr[4][2][4];   // [mi][plane][4]
            uint32_t bfr[2][2][4];   // [pair][plane][4] -> 2 n8-blocks each
            #pragma unroll
            for (int mi = 0; mi < 4; mi++) {
                const uint32_t ad = base + a_lane + (uint32_t)(mi * 16 * STRIDE_H * 2) + ko;
                LDSM4(afr[mi][0], ad);
                LDSM4(afr[mi][1], ad + TILE_BYTES);
            }
            #pragma unroll
            for (int pr = 0; pr < 2; pr++) {
                const uint32_t bd = base + 2 * TILE_BYTES + b_lane
                                  + (uint32_t)(pr * 16 * STRIDE_H * 2) + ko;
                LDSM4(bfr[pr][0], bd);
                LDSM4(bfr[pr][1], bd + TILE_BYTES);
            }
            // pass 1: hi*hi  (16 independent accumulators)
            #pragma unroll
            for (int mi = 0; mi < 4; mi++)
                #pragma unroll
                for (int ni = 0; ni < 4; ni++)
                    mma16816(acc[mi][ni], afr[mi][0], &bfr[ni >> 1][0][(ni & 1) * 2]);
            // pass 2: hi*mid
            #pragma unroll
            for (int mi = 0; mi < 4; mi++)
                #pragma unroll
                for (int ni = 0; ni < 4; ni++)
                    mma16816(acc[mi][ni], afr[mi][0], &bfr[ni >> 1][1][(ni & 1) * 2]);
            // pass 3: mid*hi
            #pragma unroll
            for (int mi = 0; mi < 4; mi++)
                #pragma unroll
                for (int ni = 0; ni < 4; ni++)
                    mma16816(acc[mi][ni], afr[mi][1], &bfr[ni >> 1][0][(ni & 1) * 2]);
        }

        if (kt + 1 < nk) {
            do_sts(buf ^ 1);
            __syncthreads();
        }
    }

    // ---- epilogue (identical to R3) ----
    if (mode == 0) {
        #pragma unroll
        for (int mi = 0; mi < 4; mi++) {
            const int grow = row0 + wm * 64 + mi * 16 + (lane >> 2);
            #pragma unroll
            for (int ni = 0; ni < 4; ni++) {
                const int gcol = col0 + wn * 32 + ni * 8 + (lane & 3) * 2;
                const float bi0 = bias[gcol], bi1 = bias[gcol + 1];
                float2 v0, v1;
                v0.x = silu(acc[mi][ni][0] + bi0);
                v0.y = silu(acc[mi][ni][1] + bi1);
                v1.x = silu(acc[mi][ni][2] + bi0);
                v1.y = silu(acc[mi][ni][3] + bi1);
                *(float2*)&C[(size_t)grow * H_DIM + gcol]       = v0;
                *(float2*)&C[(size_t)(grow + 8) * H_DIM + gcol] = v1;
            }
        }
    } else {
        const int p = blockIdx.x * 4 + wn;
        #pragma unroll
        for (int mi = 0; mi < 4; mi++) {
            float s0 = 0.0f, s1 = 0.0f;
            #pragma unroll
            for (int ni = 0; ni < 4; ni++) {
                const int gcol = col0 + wn * 32 + ni * 8 + (lane & 3) * 2;
                const float bi0 = bias[gcol], bi1 = bias[gcol + 1];
                const float w0 = Wo[gcol], w1 = Wo[gcol + 1];
                s0 += silu(acc[mi][ni][0] + bi0) * w0 + silu(acc[mi][ni][1] + bi1) * w1;
                s1 += silu(acc[mi][ni][2] + bi0) * w0 + silu(acc[mi][ni][3] + bi1) * w1;
            }
            s0 += __shfl_xor_sync(0xffffffffu, s0, 1);
            s0 += __shfl_xor_sync(0xffffffffu, s0, 2);
            s1 += __shfl_xor_sync(0xffffffffu, s1, 1);
            s1 += __shfl_xor_sync(0xffffffffu, s1, 2);
            if ((lane & 3) == 0) {
                const int r = row0 + wm * 64 + mi * 16 + (lane >> 2);
                partial[(size_t)p * M_DIM + r]     = s0;
                partial[(size_t)p * M_DIM + r + 8] = s1;
            }
        }
    }
}

// ---------------------------------------------------------------------------
// GAE reverse scan; value[m] = sum of 32 partials + bo.
// ---------------------------------------------------------------------------
__global__ void __launch_bounds__(256)
scan_kernel(const float* __restrict__ reward, const float* __restrict__ cont,
            const float* __restrict__ partial, const float* __restrict__ bo,
            float* __restrict__ out)
{
    const int b = blockIdx.x * blockDim.x + threadIdx.x;
    if (b >= B_DIM) return;
    const float bov = bo[0];

    auto val = [&](int m) {
        float s = 0.0f;
        #pragma unroll
        for (int c = 0; c < 32; c++) s += partial[(size_t)c * M_DIM + m];
        return s + bov;
    };

    float adv = 0.0f;
    float v_next = val((T_DIM - 1) * B_DIM + b);
    for (int t = T_DIM - 2; t >= 0; t--) {
        const float v0   = val(t * B_DIM + b);
        const float disc = cont[(t + 1) * B_DIM + b] * DISCOUNT;
        const float dl   = disc * LAM;
        const float delta = reward[t * B_DIM + b] + disc * v_next - v0;
        adv = delta + dl * adv;
        out[t * B_DIM + b] = adv + v0;                       // ret
        out[(T_DIM - 1) * B_DIM + t * B_DIM + b] = v0;       // baseline
        v_next = v0;
    }
}

// ---------------------------------------------------------------------------
extern "C" void kernel_launch(void* const* d_in, const int* in_sizes, int n_in,
                              void* d_out, int out_size)
{
    const float* feat   = (const float*)d_in[0];
    const float* reward = (const float*)d_in[1];
    const float* cont   = (const float*)d_in[2];
    const float* W0 = (const float*)d_in[3];
    const float* b0 = (const float*)d_in[4];
    const float* W1 = (const float*)d_in[5];
    const float* b1 = (const float*)d_in[6];
    const float* W2 = (const float*)d_in[7];
    const float* b2 = (const float*)d_in[8];
    const float* W3 = (const float*)d_in[9];
    const float* b3 = (const float*)d_in[10];
    const float* Wo = (const float*)d_in[11];
    const float* bo = (const float*)d_in[12];
    float* out = (float*)d_out;

    float *buf0, *buf1, *part;
    cudaGetSymbolAddress((void**)&buf0, g_buf0);
    cudaGetSymbolAddress((void**)&buf1, g_buf1);
    cudaGetSymbolAddress((void**)&part, g_partial);

    cudaFuncSetAttribute(gemm_hmma, cudaFuncAttributeMaxDynamicSharedMemorySize, SMEM_BYTES);

    dim3 grid(H_DIM / 128, M_DIM / 128);   // (8, 256)
    gemm_hmma<<<grid, 256, SMEM_BYTES>>>(feat, W0, b0, buf0, nullptr, nullptr, D_DIM, 0);
    gemm_hmma<<<grid, 256, SMEM_BYTES>>>(buf0, W1, b1, buf1, nullptr, nullptr, H_DIM, 0);
    gemm_hmma<<<grid, 256, SMEM_BYTES>>>(buf1, W2, b2, buf0, nullptr, nullptr, H_DIM, 0);
    gemm_hmma<<<grid, 256, SMEM_BYTES>>>(buf0, W3, b3, nullptr, Wo, part, H_DIM, 1);
    scan_kernel<<<2, 256>>>(reward, cont, part, bo, out);
}